// round 6
// baseline (speedup 1.0000x reference)
#include <cuda_runtime.h>
#include <cstdint>
#include <cstddef>

// Fixed problem dims
#define BB 4096
#define TT 256
#define DD 64
#define HH 32
#define BT (BB * TT)

// Scratch: A[b,t,j] = b1[j] + sum_{k<64} states[b,t,k] * W1[k][j]   (128 MiB)
__device__ float g_A[(size_t)BT * 32];

// ============================================================================
// Kernel 1: precompute A = states @ W1[:64,:] + b1
// Block = 256 threads = 8 warps; each warp computes 2 rows; 16 rows / block.
// W1 (64x32) and a 16x64 states tile staged in shared. k-loop: 1 broadcast LDS
// per row + 1 column LDS + 2 FFMA => 5 instr per k per 2 rows.
// ============================================================================
__global__ void __launch_bounds__(256) precompute_kernel(const float* __restrict__ states,
                                                         const float* __restrict__ W1,
                                                         const float* __restrict__ b1) {
    __shared__ float W1s[64 * 32];
    __shared__ float st[16 * 64];

    int tid = threadIdx.x;
    size_t row0 = (size_t)blockIdx.x * 16;

    for (int i = tid; i < 64 * 32; i += 256) W1s[i] = W1[i];

    // 16 contiguous rows of states = 1024 floats = 256 float4
    {
        const float4* sp = (const float4*)(states + row0 * 64);
        float4* dp = (float4*)st;
        dp[tid] = sp[tid];
    }
    __syncthreads();

    int w = tid >> 5;
    int lane = tid & 31;
    int r0 = 2 * w;
    int r1 = 2 * w + 1;

    float acc0 = __ldg(&b1[lane]);
    float acc1 = acc0;
    const float* s0 = st + r0 * 64;
    const float* s1 = st + r1 * 64;

#pragma unroll 16
    for (int k = 0; k < 64; k++) {
        float wv = W1s[k * 32 + lane];
        acc0 = fmaf(s0[k], wv, acc0);
        acc1 = fmaf(s1[k], wv, acc1);
    }

    g_A[(row0 + r0) * 32 + lane] = acc0;
    g_A[(row0 + r1) * 32 + lane] = acc1;
}

// ============================================================================
// Kernel 2: the recurrence. One warp per batch chain, lane j = hidden unit j.
// c is tracked as 4 categorical indices; fc1's categorical half is 4 shared
// row gathers. Matvecs via warp-shuffle broadcast of h (lane k holds h[k]).
// Output is the exact hard one-hot (straight-through == one-hot numerically).
// ============================================================================
__global__ void __launch_bounds__(256) recur_kernel(const float* __restrict__ gumbel,
                                                    const float* __restrict__ tau_p,
                                                    const float* __restrict__ W1,
                                                    const float* __restrict__ W2,
                                                    const float* __restrict__ b2,
                                                    const float* __restrict__ W3,
                                                    const float* __restrict__ b3,
                                                    float* __restrict__ out) {
    __shared__ float W1c[32 * 32];  // rows 64..95 of W1 (categorical part)
    __shared__ float W2s[32 * 32];
    __shared__ float W3s[32 * 32];
    __shared__ float b2s[32];
    __shared__ float b3s[32];

    int tid = threadIdx.x;
    for (int i = tid; i < 32 * 32; i += 256) {
        W1c[i] = W1[64 * 32 + i];
        W2s[i] = W2[i];
        W3s[i] = W3[i];
    }
    if (tid < 32) {
        b2s[tid] = b2[tid];
        b3s[tid] = b3[tid];
    }
    __syncthreads();

    const unsigned FULL = 0xffffffffu;
    int w = tid >> 5;
    int j = tid & 31;
    int b = blockIdx.x * 8 + w;

    float inv_tau = 1.0f / __ldg(tau_p);

    // initial c = one_hot(0) tiled -> all group indices 0
    int i0 = 0, i1 = 0, i2 = 0, i3 = 0;

    size_t base = ((size_t)b * TT) * 32 + j;
    const float* Ap = g_A + base;
    const float* Gp = gumbel + base;
    float* Op = out + base;

    float a_cur = Ap[0];
    float g_cur = Gp[0];

    for (int t = 0; t < TT; t++) {
        // prefetch next step's A and gumbel before the dependency chain
        float a_nxt = 0.0f, g_nxt = 0.0f;
        if (t < TT - 1) {
            a_nxt = Ap[(t + 1) * 32];
            g_nxt = Gp[(t + 1) * 32];
        }

        // fc1: states part precomputed (a_cur) + 4 one-hot row gathers
        float h1 = a_cur + W1c[i0 * 32 + j] + W1c[(8 + i1) * 32 + j] +
                   W1c[(16 + i2) * 32 + j] + W1c[(24 + i3) * 32 + j];
        h1 = fmaxf(h1, 0.0f);

        // fc2: h2[j] = b2[j] + sum_k h1[k] * W2[k][j]
        float h2 = b2s[j];
#pragma unroll
        for (int k = 0; k < 32; k++)
            h2 = fmaf(__shfl_sync(FULL, h1, k), W2s[k * 32 + j], h2);
        h2 = fmaxf(h2, 0.0f);

        // fc3: q[j] = b3[j] + sum_k h2[k] * W3[k][j]
        float q = b3s[j];
#pragma unroll
        for (int k = 0; k < 32; k++)
            q = fmaf(__shfl_sync(FULL, h2, k), W3s[k * 32 + j], q);

        // gumbel-softmax hard sample == argmax of (q+g)/tau within each group of 8
        float v = (q + g_cur) * inv_tau;
        int ii = j & 7;
#pragma unroll
        for (int off = 4; off >= 1; off >>= 1) {
            float ov = __shfl_xor_sync(FULL, v, off);
            int oi = __shfl_xor_sync(FULL, ii, off);
            if (ov > v || (ov == v && oi < ii)) {  // first-occurrence tie-break
                v = ov;
                ii = oi;
            }
        }

        // straight-through output is exactly the hard one-hot
        Op[t * 32] = (ii == (j & 7)) ? 1.0f : 0.0f;

        // broadcast the 4 group winners to all lanes for the next step
        i0 = __shfl_sync(FULL, ii, 0);
        i1 = __shfl_sync(FULL, ii, 8);
        i2 = __shfl_sync(FULL, ii, 16);
        i3 = __shfl_sync(FULL, ii, 24);

        a_cur = a_nxt;
        g_cur = g_nxt;
    }
}

// ============================================================================
// Launch
// ============================================================================
extern "C" void kernel_launch(void* const* d_in, const int* in_sizes, int n_in,
                              void* d_out, int out_size) {
    const float* states = (const float*)d_in[0];  // [B,T,64]
    const float* gumbel = (const float*)d_in[1];  // [B,T,4,8]
    const float* tau    = (const float*)d_in[2];  // scalar
    const float* W1     = (const float*)d_in[3];  // [96,32]
    const float* b1     = (const float*)d_in[4];  // [32]
    const float* W2     = (const float*)d_in[5];  // [32,32]
    const float* b2     = (const float*)d_in[6];  // [32]
    const float* W3     = (const float*)d_in[7];  // [32,32]
    const float* b3     = (const float*)d_in[8];  // [32]
    float* out = (float*)d_out;                   // [B,T,32]

    precompute_kernel<<<BT / 16, 256>>>(states, W1, b1);
    recur_kernel<<<BB / 8, 256>>>(gumbel, tau, W1, W2, b2, W3, b3, out);
}

// round 7
// speedup vs baseline: 1.2735x; 1.2735x over previous
#include <cuda_runtime.h>
#include <cstdint>
#include <cstddef>

typedef unsigned long long ull;

// Fixed problem dims
#define BB 4096
#define TT 256
#define DD 64
#define HH 32
#define BT (BB * TT)

// Scratch: A[b,t,j] = b1[j] + sum_{k<64} states[b,t,k] * W1[k][j]   (128 MiB)
__device__ float g_A[(size_t)BT * 32];

static __device__ __forceinline__ ull pack2(float lo, float hi) {
    ull r;
    asm("mov.b64 %0, {%1, %2};" : "=l"(r) : "f"(lo), "f"(hi));
    return r;
}
static __device__ __forceinline__ void unpack2(ull v, float& lo, float& hi) {
    asm("mov.b64 {%0, %1}, %2;" : "=f"(lo), "=f"(hi) : "l"(v));
}
static __device__ __forceinline__ void ffma2(ull& acc, ull a, ull b) {
    asm("fma.rn.f32x2 %0, %1, %2, %0;" : "+l"(acc) : "l"(a), "l"(b));
}

// ============================================================================
// Kernel 1: A = states @ W1[:64,:] + b1 via packed f32x2.
// Block = 256 thr = 8 warps, 32 rows/block. Warp w computes rows 4w..4w+3 as
// two row-pairs packed in f32x2 accumulators. Inner k-loop:
//   2x LDS.64 (row-pair of s, broadcast) + 1x LDS.64 (dup'd weight) + 2x FFMA2
// = 5 instr per k for 4 rows (vs 5/k for 2 rows scalar), FFMA pipe halved.
// ============================================================================
#define PC_ROWS 32
#define ST_PAD 17  // ull stride per k for st2 (16 row-pairs + 1 pad)

__global__ void __launch_bounds__(256) precompute_kernel(const float* __restrict__ states,
                                                         const float* __restrict__ W1,
                                                         const float* __restrict__ b1) {
    __shared__ ull w1d[64 * 32];       // w1d[k*32+j] = {W1[k][j], W1[k][j]}  (16 KB)
    __shared__ ull st2[64 * ST_PAD];   // st2[k*17+rp] = {s[2rp][k], s[2rp+1][k]}

    int tid = threadIdx.x;
    size_t row0 = (size_t)blockIdx.x * PC_ROWS;

    // stage duplicated W1 (rows 0..63)
    for (int i = tid; i < 64 * 32; i += 256) {
        float w = W1[i];
        w1d[i] = pack2(w, w);
    }

    // stage states tile transposed into row-pair-packed layout
    {
        const float4* sp = (const float4*)(states + row0 * 64);
        float* stf = (float*)st2;
#pragma unroll
        for (int it = 0; it < 2; it++) {
            int v = tid + it * 256;        // 512 float4 = 32 rows x 16
            int r = v >> 4;
            int k4 = (v & 15) * 4;
            float4 f = sp[v];
            int rp = r >> 1, par = r & 1;
            stf[((k4 + 0) * ST_PAD + rp) * 2 + par] = f.x;
            stf[((k4 + 1) * ST_PAD + rp) * 2 + par] = f.y;
            stf[((k4 + 2) * ST_PAD + rp) * 2 + par] = f.z;
            stf[((k4 + 3) * ST_PAD + rp) * 2 + par] = f.w;
        }
    }
    __syncthreads();

    int w = tid >> 5;
    int j = tid & 31;
    int rp0 = 2 * w;      // rows 4w, 4w+1
    int rp1 = 2 * w + 1;  // rows 4w+2, 4w+3

    float bj = __ldg(&b1[j]);
    ull acc0 = pack2(bj, bj);
    ull acc1 = acc0;

#pragma unroll
    for (int k = 0; k < 64; k++) {
        ull s0 = st2[k * ST_PAD + rp0];
        ull s1 = st2[k * ST_PAD + rp1];
        ull wd = w1d[k * 32 + j];
        ffma2(acc0, s0, wd);
        ffma2(acc1, s1, wd);
    }

    float a00, a01, a10, a11;
    unpack2(acc0, a00, a01);
    unpack2(acc1, a10, a11);
    float* gp = g_A + (row0 + 4 * w) * 32 + j;
    gp[0]  = a00;
    gp[32] = a01;
    gp[64] = a10;
    gp[96] = a11;
}

// ============================================================================
// Kernel 2: recurrence. One warp per chain, lane j = hidden unit j.
// W2/W3 columns register-resident per lane (no LDS in the matvec loops),
// 4-way split accumulators to break the serial FMA chain, /tau dropped
// (monotone for argmax). Output is the exact hard one-hot.
// ============================================================================
__global__ void __launch_bounds__(128) recur_kernel(const float* __restrict__ gumbel,
                                                    const float* __restrict__ W1,
                                                    const float* __restrict__ W2,
                                                    const float* __restrict__ b2,
                                                    const float* __restrict__ W3,
                                                    const float* __restrict__ b3,
                                                    float* __restrict__ out) {
    __shared__ float W1c[32 * 32];  // rows 64..95 of W1 (categorical part)

    int tid = threadIdx.x;
    for (int i = tid; i < 32 * 32; i += 128) W1c[i] = W1[64 * 32 + i];
    __syncthreads();

    const unsigned FULL = 0xffffffffu;
    int w = tid >> 5;
    int j = tid & 31;
    int b = blockIdx.x * 4 + w;

    // register-resident weight columns: lane j owns W2[:,j], W3[:,j]
    float W2c[32], W3c[32];
#pragma unroll
    for (int k = 0; k < 32; k++) {
        W2c[k] = __ldg(&W2[k * 32 + j]);
        W3c[k] = __ldg(&W3[k * 32 + j]);
    }
    float b2j = __ldg(&b2[j]);
    float b3j = __ldg(&b3[j]);

    int i0 = 0, i1 = 0, i2 = 0, i3 = 0;  // initial c = one_hot(0) per group

    size_t base = ((size_t)b * TT) * 32 + j;
    const float* Ap = g_A + base;
    const float* Gp = gumbel + base;
    float* Op = out + base;

    float a_cur = Ap[0];
    float g_cur = Gp[0];
    int jg = j & 7;

    for (int t = 0; t < TT; t++) {
        float a_nxt = 0.0f, g_nxt = 0.0f;
        if (t < TT - 1) {
            a_nxt = Ap[(t + 1) * 32];
            g_nxt = Gp[(t + 1) * 32];
        }

        // fc1: precomputed states part + 4 one-hot row gathers
        float h1 = a_cur + W1c[i0 * 32 + j] + W1c[(8 + i1) * 32 + j] +
                   W1c[(16 + i2) * 32 + j] + W1c[(24 + i3) * 32 + j];
        h1 = fmaxf(h1, 0.0f);

        // fc2: h2[j] = b2[j] + sum_k h1[k]*W2[k][j], 4 split accumulators
        float s0 = b2j, s1 = 0.0f, s2 = 0.0f, s3 = 0.0f;
#pragma unroll
        for (int k = 0; k < 32; k += 4) {
            s0 = fmaf(__shfl_sync(FULL, h1, k + 0), W2c[k + 0], s0);
            s1 = fmaf(__shfl_sync(FULL, h1, k + 1), W2c[k + 1], s1);
            s2 = fmaf(__shfl_sync(FULL, h1, k + 2), W2c[k + 2], s2);
            s3 = fmaf(__shfl_sync(FULL, h1, k + 3), W2c[k + 3], s3);
        }
        float h2 = fmaxf((s0 + s1) + (s2 + s3), 0.0f);

        // fc3: q[j] = b3[j] + sum_k h2[k]*W3[k][j]
        float q0 = b3j, q1 = 0.0f, q2 = 0.0f, q3 = 0.0f;
#pragma unroll
        for (int k = 0; k < 32; k += 4) {
            q0 = fmaf(__shfl_sync(FULL, h2, k + 0), W3c[k + 0], q0);
            q1 = fmaf(__shfl_sync(FULL, h2, k + 1), W3c[k + 1], q1);
            q2 = fmaf(__shfl_sync(FULL, h2, k + 2), W3c[k + 2], q2);
            q3 = fmaf(__shfl_sync(FULL, h2, k + 3), W3c[k + 3], q3);
        }
        float q = (q0 + q1) + (q2 + q3);

        // hard gumbel-softmax sample == argmax(q + g) per group of 8
        // (softmax and /tau are strictly monotone -> skipped)
        float v = q + g_cur;
        int ii = jg;
#pragma unroll
        for (int off = 4; off >= 1; off >>= 1) {
            float ov = __shfl_xor_sync(FULL, v, off);
            int oi = __shfl_xor_sync(FULL, ii, off);
            if (ov > v || (ov == v && oi < ii)) {  // first-index tie-break
                v = ov;
                ii = oi;
            }
        }

        // straight-through forward output == exact hard one-hot
        Op[t * 32] = (ii == jg) ? 1.0f : 0.0f;

        // broadcast the 4 group winners for next step's fc1 gathers
        i0 = __shfl_sync(FULL, ii, 0);
        i1 = __shfl_sync(FULL, ii, 8);
        i2 = __shfl_sync(FULL, ii, 16);
        i3 = __shfl_sync(FULL, ii, 24);

        a_cur = a_nxt;
        g_cur = g_nxt;
    }
}

// ============================================================================
// Launch
// ============================================================================
extern "C" void kernel_launch(void* const* d_in, const int* in_sizes, int n_in,
                              void* d_out, int out_size) {
    const float* states = (const float*)d_in[0];  // [B,T,64]
    const float* gumbel = (const float*)d_in[1];  // [B,T,4,8]
    // d_in[2] = tau (unused: monotone under argmax)
    const float* W1     = (const float*)d_in[3];  // [96,32]
    const float* b1     = (const float*)d_in[4];  // [32]
    const float* W2     = (const float*)d_in[5];  // [32,32]
    const float* b2     = (const float*)d_in[6];  // [32]
    const float* W3     = (const float*)d_in[7];  // [32,32]
    const float* b3     = (const float*)d_in[8];  // [32]
    float* out = (float*)d_out;                   // [B,T,32]

    precompute_kernel<<<BT / PC_ROWS, 256>>>(states, W1, b1);
    recur_kernel<<<BB / 4, 128>>>(gumbel, W1, W2, b2, W3, b3, out);
}

// round 9
// speedup vs baseline: 2.0233x; 1.5888x over previous
#include <cuda_runtime.h>
#include <cstdint>
#include <cstddef>

typedef unsigned long long ull;

#define BB 4096
#define TT 256
#define DD 64
#define HH 32
#define BT (BB * TT)

// Scratch: A[b,t,j] = b1[j] + sum_{k<64} states[b,t,k] * W1[k][j]   (128 MiB)
__device__ float g_A[(size_t)BT * 32];

// ---------- packed f32x2 helpers ----------
static __device__ __forceinline__ ull pack2(float lo, float hi) {
    ull r;
    asm("mov.b64 %0, {%1, %2};" : "=l"(r) : "f"(lo), "f"(hi));
    return r;
}
static __device__ __forceinline__ void unpack2(ull v, float& lo, float& hi) {
    asm("mov.b64 {%0, %1}, %2;" : "=f"(lo), "=f"(hi) : "l"(v));
}
static __device__ __forceinline__ void ffma2(ull& acc, ull a, ull b) {
    asm("fma.rn.f32x2 %0, %1, %2, %0;" : "+l"(acc) : "l"(a), "l"(b));
}
static __device__ __forceinline__ ull addx2(ull a, ull b) {
    ull r;
    asm("add.rn.f32x2 %0, %1, %2;" : "=l"(r) : "l"(a), "l"(b));
    return r;
}
static __device__ __forceinline__ void lds_v2u64(ull& a, ull& b, uint32_t addr) {
    asm volatile("ld.shared.v2.b64 {%0, %1}, [%2];" : "=l"(a), "=l"(b) : "r"(addr) : "memory");
}
static __device__ __forceinline__ void sts_f32(uint32_t addr, float v) {
    asm volatile("st.shared.f32 [%0], %1;" :: "r"(addr), "f"(v) : "memory");
}
static __device__ __forceinline__ uint32_t smem_u32(const void* p) {
    return (uint32_t)__cvta_generic_to_shared(p);
}

// ============================================================================
// Kernel 1: A = states @ W1[:64,:] + b1
// Block = 256 thr = 8 warps, 64 rows/block. States staged TRANSPOSED as
// row-pair-packed u64: stp[k*ST + rp] = {s[2rp][k], s[2rp+1][k]}.
// Warp w owns rps 4w..4w+3 (8 rows). Inner k: 2x ld.shared.v2.b64 (broadcast,
// 1 phase each, 4 rows per load) + 4x FFMA2 with weight pairs {w,w} in
// chunked REGISTERS (no smem phase). Phases/row ~25 vs 64 before.
// ============================================================================
#define PT_ROWS 64
#define ST 34  // ull stride per k (32 rps + 2 pad)

__global__ void __launch_bounds__(256) precompute_kernel(const float* __restrict__ states,
                                                         const float* __restrict__ W1,
                                                         const float* __restrict__ b1) {
    __shared__ __align__(16) ull stp[64 * ST];   // 17408 B
    __shared__ float W1s[64 * 32];               // 8192 B

    int tid = threadIdx.x;
    size_t row0 = (size_t)blockIdx.x * PT_ROWS;

    // stage W1 rows 0..63
    for (int i = tid; i < 64 * 32; i += 256) W1s[i] = W1[i];

    // stage states transposed + row-pair packed.
    // thread: rp = tid>>3 (0..31), ks = tid&7; covers k4 in {ks, ks+8}.
    {
        int rp = tid >> 3;
        int ks = tid & 7;
        const float* base = states + (row0 + 2 * (size_t)rp) * 64;
#pragma unroll
        for (int h = 0; h < 2; h++) {
            int k4 = ks + 8 * h;
            float4 fa = *(const float4*)(base + k4 * 4);
            float4 fb = *(const float4*)(base + 64 + k4 * 4);
            stp[(k4 * 4 + 0) * ST + rp] = pack2(fa.x, fb.x);
            stp[(k4 * 4 + 1) * ST + rp] = pack2(fa.y, fb.y);
            stp[(k4 * 4 + 2) * ST + rp] = pack2(fa.z, fb.z);
            stp[(k4 * 4 + 3) * ST + rp] = pack2(fa.w, fb.w);
        }
    }
    __syncthreads();

    int w = tid >> 5;
    int j = tid & 31;

    ull acc0 = 0, acc1 = 0, acc2 = 0, acc3 = 0;  // rps 4w..4w+3 (rows 8w..8w+7)
    uint32_t stp_base = smem_u32(stp);

#pragma unroll 1
    for (int ch = 0; ch < 2; ch++) {
        ull wd[32];
#pragma unroll
        for (int kk = 0; kk < 32; kk++) {
            float wv = W1s[(32 * ch + kk) * 32 + j];
            wd[kk] = pack2(wv, wv);
        }
#pragma unroll
        for (int kk = 0; kk < 32; kk++) {
            int k = 32 * ch + kk;
            ull pA0, pA1, pB0, pB1;
            lds_v2u64(pA0, pA1, stp_base + (k * ST + 4 * w) * 8);
            lds_v2u64(pB0, pB1, stp_base + (k * ST + 4 * w + 2) * 8);
            ffma2(acc0, pA0, wd[kk]);
            ffma2(acc1, pA1, wd[kk]);
            ffma2(acc2, pB0, wd[kk]);
            ffma2(acc3, pB1, wd[kk]);
        }
    }

    float bj = __ldg(&b1[j]);
    float lo, hi;
    float* gp = g_A + (row0 + 8 * (size_t)w) * 32 + j;
    unpack2(acc0, lo, hi); gp[0 * 32] = bj + lo; gp[1 * 32] = bj + hi;
    unpack2(acc1, lo, hi); gp[2 * 32] = bj + lo; gp[3 * 32] = bj + hi;
    unpack2(acc2, lo, hi); gp[4 * 32] = bj + lo; gp[5 * 32] = bj + hi;
    unpack2(acc3, lo, hi); gp[6 * 32] = bj + lo; gp[7 * 32] = bj + hi;
}

// ============================================================================
// Kernel 2: recurrence. Block = 64 thr = 2 warps; each warp runs TWO chains
// (independent dep chains -> ILP). Matvec: h staged to per-warp smem buffer,
// __syncwarp, 8x ld.shared.v2.b64 gives (h[2i],h[2i+1]) pairs feeding
// fma.rn.f32x2 against register-resident packed weight pairs.
// Hazards: STS h1 -> sync1 -> LDS fc2 (bufX) ; STS h2 -> sync2 -> LDS fc3
// (bufY). sync2 also orders fc2's bufX reads before next step's bufX writes.
// ============================================================================

// 16-FFMA2 matvec: base = smem addr of 32-float h vector; Wp[i]={W[2i][j],W[2i+1][j]}
static __device__ __forceinline__ float matvec32(uint32_t base, const ull* Wp, float bias) {
    ull a0 = 0, a1 = 0, a2 = 0, a3 = 0;
#pragma unroll
    for (int l = 0; l < 8; l++) {
        ull p0, p1;
        lds_v2u64(p0, p1, base + l * 16);
        if (l & 1) {
            ffma2(a2, p0, Wp[2 * l]);
            ffma2(a3, p1, Wp[2 * l + 1]);
        } else {
            ffma2(a0, p0, Wp[2 * l]);
            ffma2(a1, p1, Wp[2 * l + 1]);
        }
    }
    ull s = addx2(addx2(a0, a2), addx2(a1, a3));
    float lo, hi;
    unpack2(s, lo, hi);
    return bias + (lo + hi);
}

__global__ void __launch_bounds__(64) recur_kernel(const float* __restrict__ gumbel,
                                                   const float* __restrict__ W1,
                                                   const float* __restrict__ W2,
                                                   const float* __restrict__ b2,
                                                   const float* __restrict__ W3,
                                                   const float* __restrict__ b3,
                                                   float* __restrict__ out) {
    __shared__ float W1c[32 * 32];                       // rows 64..95 of W1
    __shared__ __align__(16) float bufx[2][2][32];       // [warp][chain][32] : h1
    __shared__ __align__(16) float bufy[2][2][32];       // h2

    int tid = threadIdx.x;
    for (int i = tid; i < 32 * 32; i += 64) W1c[i] = W1[64 * 32 + i];
    __syncthreads();

    const unsigned FULL = 0xffffffffu;
    int w = tid >> 5;
    int j = tid & 31;
    int jg = j & 7;

    // packed weight pairs (shared by both chains)
    ull W2p[16], W3p[16];
#pragma unroll
    for (int i = 0; i < 16; i++) {
        W2p[i] = pack2(__ldg(&W2[(2 * i) * 32 + j]), __ldg(&W2[(2 * i + 1) * 32 + j]));
        W3p[i] = pack2(__ldg(&W3[(2 * i) * 32 + j]), __ldg(&W3[(2 * i + 1) * 32 + j]));
    }
    float b2j = __ldg(&b2[j]);
    float b3j = __ldg(&b3[j]);

    uint32_t bx[2], by[2], bxj[2], byj[2];
#pragma unroll
    for (int c = 0; c < 2; c++) {
        bx[c] = smem_u32(&bufx[w][c][0]);
        by[c] = smem_u32(&bufy[w][c][0]);
        bxj[c] = bx[c] + 4 * j;
        byj[c] = by[c] + 4 * j;
    }

    const float* Ap[2];
    const float* Gp[2];
    float* Op[2];
    float a_cur[2], g_cur[2];
    int i0[2], i1[2], i2[2], i3[2];

#pragma unroll
    for (int c = 0; c < 2; c++) {
        int b = blockIdx.x * 4 + 2 * w + c;
        size_t base = ((size_t)b * TT) * 32 + j;
        Ap[c] = g_A + base;
        Gp[c] = gumbel + base;
        Op[c] = out + base;
        a_cur[c] = Ap[c][0];
        g_cur[c] = Gp[c][0];
        i0[c] = i1[c] = i2[c] = i3[c] = 0;
    }

    for (int t = 0; t < TT; t++) {
        // prefetch next step inputs ahead of the serial chain
        float a_n[2] = {0.f, 0.f}, g_n[2] = {0.f, 0.f};
        if (t + 1 < TT) {
#pragma unroll
            for (int c = 0; c < 2; c++) {
                a_n[c] = Ap[c][(t + 1) * 32];
                g_n[c] = Gp[c][(t + 1) * 32];
            }
        }

        // fc1 (+relu) and stage h1
#pragma unroll
        for (int c = 0; c < 2; c++) {
            float h1 = a_cur[c] + W1c[i0[c] * 32 + j] + W1c[(8 + i1[c]) * 32 + j] +
                       W1c[(16 + i2[c]) * 32 + j] + W1c[(24 + i3[c]) * 32 + j];
            h1 = fmaxf(h1, 0.0f);
            sts_f32(bxj[c], h1);
        }
        __syncwarp();

        // fc2 (+relu), stage h2
        float h2v[2];
#pragma unroll
        for (int c = 0; c < 2; c++)
            h2v[c] = fmaxf(matvec32(bx[c], W2p, b2j), 0.0f);
#pragma unroll
        for (int c = 0; c < 2; c++) sts_f32(byj[c], h2v[c]);
        __syncwarp();

        // fc3, add gumbel (tau/softmax monotone -> argmax only)
        float v[2];
        int ii[2];
#pragma unroll
        for (int c = 0; c < 2; c++) {
            v[c] = matvec32(by[c], W3p, b3j) + g_cur[c];
            ii[c] = jg;
        }

        // per-group argmax butterfly, interleaved across chains
#pragma unroll
        for (int off = 4; off >= 1; off >>= 1) {
#pragma unroll
            for (int c = 0; c < 2; c++) {
                float ov = __shfl_xor_sync(FULL, v[c], off);
                int oi = __shfl_xor_sync(FULL, ii[c], off);
                if (ov > v[c] || (ov == v[c] && oi < ii[c])) {  // first-index tie-break
                    v[c] = ov;
                    ii[c] = oi;
                }
            }
        }

#pragma unroll
        for (int c = 0; c < 2; c++) {
            // straight-through forward == exact hard one-hot
            Op[c][t * 32] = (ii[c] == jg) ? 1.0f : 0.0f;
            i0[c] = __shfl_sync(FULL, ii[c], 0);
            i1[c] = __shfl_sync(FULL, ii[c], 8);
            i2[c] = __shfl_sync(FULL, ii[c], 16);
            i3[c] = __shfl_sync(FULL, ii[c], 24);
            a_cur[c] = a_n[c];
            g_cur[c] = g_n[c];
        }
    }
}

// ============================================================================
// Launch
// ============================================================================
extern "C" void kernel_launch(void* const* d_in, const int* in_sizes, int n_in,
                              void* d_out, int out_size) {
    const float* states = (const float*)d_in[0];  // [B,T,64]
    const float* gumbel = (const float*)d_in[1];  // [B,T,4,8]
    // d_in[2] = tau (unused: monotone under argmax)
    const float* W1     = (const float*)d_in[3];  // [96,32]
    const float* b1     = (const float*)d_in[4];  // [32]
    const float* W2     = (const float*)d_in[5];  // [32,32]
    const float* b2     = (const float*)d_in[6];  // [32]
    const float* W3     = (const float*)d_in[7];  // [32,32]
    const float* b3     = (const float*)d_in[8];  // [32]
    float* out = (float*)d_out;                   // [B,T,32]

    precompute_kernel<<<BT / PT_ROWS, 256>>>(states, W1, b1);
    recur_kernel<<<BB / 4, 64>>>(gumbel, W1, W2, b2, W3, b3, out);
}